// round 10
// baseline (speedup 1.0000x reference)
#include <cuda_runtime.h>
#include <cuda_bf16.h>

// out[t, e] = cos(t) * s[e] + b[e],  s[e] = sum_q W[e,q]
// E = 1024, T = out_size / E.
//
// R9: bulk pipeline is latency-bound per CTA (everything at 40-50%, ~5.6k
// cycles per 24KB iter vs ~1.5k of real work). Hybrid: keep the 6-row
// smem->bulk pipeline AND have every thread also write 4 rows directly via
// STG.128 in the shadow of the bulk handshake. The two store paths (L1tex
// STG vs bulk engine) are disjoint until L2, which has headroom.

#define RPB 6          // rows per bulk group (6 x 4KB = 24KB)
#define RPD 4          // rows stored directly via STG per iteration
#define RPI (RPB + RPD)
#define EROW 1024      // embed dim (compile-time for smem layout; checked at launch)

__global__ __launch_bounds__(256)
void pequant_hybrid_kernel(const float* __restrict__ W,
                           const float* __restrict__ b,
                           float* __restrict__ out,
                           int T, int Q) {
    __shared__ __align__(128) float buf[2][RPB * EROW];   // 48 KB

    const int tid = threadIdx.x;          // 0..255
    const int e0  = tid * 4;

    // Per-thread row constants: s[j] = sum_q W[e0+j, q], bb[j] = b[e0+j].
    float s[4], bb[4];
#pragma unroll
    for (int j = 0; j < 4; j++) {
        const int e = e0 + j;
        float acc = 0.0f;
        const float* wr = W + (size_t)e * Q;
#pragma unroll 8
        for (int q = 0; q < Q; q++) acc += __ldg(wr + q);
        s[j]  = acc;
        bb[j] = __ldg(b + e);
    }

    const unsigned sm0 = (unsigned)__cvta_generic_to_shared(&buf[0][0]);
    const unsigned sm1 = (unsigned)__cvta_generic_to_shared(&buf[1][0]);

    const int stride = gridDim.x * RPI;
    int k = 0;
    for (int base = blockIdx.x * RPI; base < T; base += stride, ++k) {
        const int ph = k & 1;

        // Reuse buffer ph only after its bulk store (issued 2 iterations ago)
        // finished READING smem. Group from last iteration may stay in flight.
        if (k >= 2 && tid == 0)
            asm volatile("cp.async.bulk.wait_group.read 1;" ::: "memory");
        __syncthreads();

        const int rows  = min(RPI, T - base);
        const int brows = min(RPB, rows);           // rows via bulk
        float* bp = buf[ph];

        // Fill bulk buffer: rows [base, base+brows)
        if (brows == RPB) {
#pragma unroll
            for (int r = 0; r < RPB; r++) {
                const float c = cosf((float)(base + r));
                float4 v;
                v.x = fmaf(c, s[0], bb[0]);
                v.y = fmaf(c, s[1], bb[1]);
                v.z = fmaf(c, s[2], bb[2]);
                v.w = fmaf(c, s[3], bb[3]);
                *reinterpret_cast<float4*>(bp + r * EROW + e0) = v;
            }
        } else {
            for (int r = 0; r < brows; r++) {
                const float c = cosf((float)(base + r));
                float4 v;
                v.x = fmaf(c, s[0], bb[0]);
                v.y = fmaf(c, s[1], bb[1]);
                v.z = fmaf(c, s[2], bb[2]);
                v.w = fmaf(c, s[3], bb[3]);
                *reinterpret_cast<float4*>(bp + r * EROW + e0) = v;
            }
        }
        __syncthreads();

        if (tid == 0) {
            // Order this CTA's generic-proxy STS before the async-proxy read.
            asm volatile("fence.proxy.async.shared::cta;" ::: "memory");
            const unsigned src = ph ? sm1 : sm0;
            asm volatile(
                "cp.async.bulk.global.shared::cta.bulk_group [%0], [%1], %2;"
                :: "l"(out + (size_t)base * EROW), "r"(src),
                   "r"(brows * (EROW * 4))
                : "memory");
            asm volatile("cp.async.bulk.commit_group;" ::: "memory");
        }

        // Direct-STG rows [base+RPB, base+rows) — issued while the bulk
        // engine drains the buffer; fire-and-forget through L1tex.
        const int drows = rows - RPB;
        if (drows == RPD) {
#pragma unroll
            for (int r = 0; r < RPD; r++) {
                const int t = base + RPB + r;
                const float c = cosf((float)t);
                float4 v;
                v.x = fmaf(c, s[0], bb[0]);
                v.y = fmaf(c, s[1], bb[1]);
                v.z = fmaf(c, s[2], bb[2]);
                v.w = fmaf(c, s[3], bb[3]);
                *reinterpret_cast<float4*>(out + (size_t)t * EROW + e0) = v;
            }
        } else if (drows > 0) {
            for (int r = 0; r < drows; r++) {
                const int t = base + RPB + r;
                const float c = cosf((float)t);
                float4 v;
                v.x = fmaf(c, s[0], bb[0]);
                v.y = fmaf(c, s[1], bb[1]);
                v.z = fmaf(c, s[2], bb[2]);
                v.w = fmaf(c, s[3], bb[3]);
                *reinterpret_cast<float4*>(out + (size_t)t * EROW + e0) = v;
            }
        }
    }

    // Drain all outstanding bulk stores before exit.
    if (tid == 0)
        asm volatile("cp.async.bulk.wait_group 0;" ::: "memory");
}

// Fallback (direct STG) for the E != 1024 case — never expected here.
__global__ __launch_bounds__(256, 8)
void pequant_fallback_kernel(const float* __restrict__ W,
                             const float* __restrict__ b,
                             float* __restrict__ out,
                             int T, int E, int Q) {
    const int tid = threadIdx.x;
    const int e0  = tid * 4;
    float s[4], bb[4];
#pragma unroll
    for (int j = 0; j < 4; j++) {
        const int e = e0 + j;
        float acc = 0.0f;
        const float* wr = W + (size_t)e * Q;
        for (int q = 0; q < Q; q++) acc += wr[q];
        s[j]  = acc;
        bb[j] = b[e];
    }
    for (int t = blockIdx.x; t < T; t += gridDim.x) {
        const float c = cosf((float)t);
        float4 v;
        v.x = fmaf(c, s[0], bb[0]);
        v.y = fmaf(c, s[1], bb[1]);
        v.z = fmaf(c, s[2], bb[2]);
        v.w = fmaf(c, s[3], bb[3]);
        *reinterpret_cast<float4*>(out + (size_t)t * E + e0) = v;
    }
}

extern "C" void kernel_launch(void* const* d_in, const int* in_sizes, int n_in,
                              void* d_out, int out_size) {
    // metadata order: x (unused), W [E, Q], b [E]
    const float* W = (const float*)d_in[1];
    const float* b = (const float*)d_in[2];
    float* out = (float*)d_out;

    const int E = in_sizes[2];            // 1024
    const int Q = in_sizes[1] / E;        // 8
    const int T = out_size / E;           // 65536

    if (E == EROW) {
        const int chunks = (T + RPI - 1) / RPI;   // 6554
        int blocks = 148 * 4;                      // 4 CTAs/SM @ 48 KB smem
        if (blocks > chunks) blocks = chunks;
        pequant_hybrid_kernel<<<blocks, EROW / 4>>>(W, b, out, T, Q);
    } else {
        int blocks = 2048;
        if (blocks > T) blocks = T;
        pequant_fallback_kernel<<<blocks, E / 4>>>(W, b, out, T, E, Q);
    }
}